// round 9
// baseline (speedup 1.0000x reference)
#include <cuda_runtime.h>

// SidedDistance: argmin_j ||S1[b,n]-S2[b,j]||^2, B=4, N=M=8192. Output = float32 indices.
//
// Bit-exact contract (validated R5/R7/R8): reproduce reference f32 lowering exactly:
//   cross = fma(z,sz, fma(y,sy, fl(x*sx)))
//   n     = fl(fl(fl(x^2)+fl(y^2))+fl(z^2))
//   d2    = fl(fl(n1 - 2*cross) + n2)     [== fl(fma(cross,-2,n1) + n2), 2c exact]
//   argmin: first index achieving the min.
//
// K1 (pass1): packed f32x2 value-only min, per-chunk(256) memoized; winning chunk
//   per query (value, then smaller base) -> g_base. Changes this round:
//   - pack/unpack via register-alias bitcasts (no mov.b64 asm)  [~ -12% inst]
//   - grid = 148 blocks (4 x 37), uneven 222/200 queries/block  [x0.867 makespan]
// K2 (pass2): one warp per query, coalesced rescan of the 256-cand winning chunk,
//   exact arithmetic, (value, then index) warp argmin-reduce.

#define NBATCH   4
#define NQ       8192
#define M        8192
#define THREADS  512
#define G        4
#define SLOTS    128
#define QBMAX    256                  // slot capacity (2 per slot)
#define QCHUNKS  37                   // query-chunks per batch
#define QB_STD   222                  // queries per block (last block: 200)
#define TILE     2048
#define NTILE    (M / TILE)           // 4
#define QTR      (TILE / G)           // 512
#define CHUNK    256
#define CPT      (QTR / CHUNK)        // 2
#define NCHUNK   (NTILE * CPT)        // 8

typedef unsigned long long u64;

__device__ int g_base[NBATCH * NQ];

__device__ __forceinline__ u64 pk2c(float lo, float hi) {
    return (u64)(unsigned)__float_as_int(lo) | ((u64)(unsigned)__float_as_int(hi) << 32);
}
__device__ __forceinline__ float lo2(u64 v) { return __int_as_float((int)(unsigned)v); }
__device__ __forceinline__ float hi2(u64 v) { return __int_as_float((int)(unsigned)(v >> 32)); }
__device__ __forceinline__ u64 mul2(u64 a, u64 b) {
    u64 r; asm("mul.rn.f32x2 %0, %1, %2;" : "=l"(r) : "l"(a), "l"(b)); return r;
}
__device__ __forceinline__ u64 add2(u64 a, u64 b) {
    u64 r; asm("add.rn.f32x2 %0, %1, %2;" : "=l"(r) : "l"(a), "l"(b)); return r;
}
__device__ __forceinline__ u64 fma2_(u64 a, u64 b, u64 c) {
    u64 r; asm("fma.rn.f32x2 %0, %1, %2, %3;" : "=l"(r) : "l"(a), "l"(b), "l"(c)); return r;
}

// ---------------- Kernel 1 ----------------
__global__ __launch_bounds__(THREADS, 1)
void SidedDistance_pass1(const float* __restrict__ S1,
                         const float* __restrict__ S2)
{
    __shared__ __align__(16) float xs[TILE];
    __shared__ __align__(16) float ys[TILE];
    __shared__ __align__(16) float zs[TILE];
    __shared__ __align__(16) float ws[TILE];
    __shared__ float pv[G][QBMAX];
    __shared__ int   pb[G][QBMAX];

    const int b      = blockIdx.x / QCHUNKS;
    const int qc     = blockIdx.x % QCHUNKS;
    const int qbase  = qc * QB_STD;
    const int qcount = min(QB_STD, NQ - qbase);      // 222 or 200 (even)
    const int tid    = threadIdx.x;
    const int slot   = tid & (SLOTS - 1);
    const int g      = tid >> 7;
    const int ql0    = 2 * slot;
    const int ql1    = 2 * slot + 1;
    const bool valid = (ql1 < qcount);

    // queries + n1 (reference rounding); guard OOB for idle slots
    const float* s1b = S1 + ((size_t)b * NQ + qbase) * 3;
    float ax0 = 0.f, ay0 = 0.f, az0 = 0.f, ax1 = 0.f, ay1 = 0.f, az1 = 0.f;
    if (valid) {
        ax0 = s1b[3 * ql0 + 0]; ay0 = s1b[3 * ql0 + 1]; az0 = s1b[3 * ql0 + 2];
        ax1 = s1b[3 * ql1 + 0]; ay1 = s1b[3 * ql1 + 1]; az1 = s1b[3 * ql1 + 2];
    }
    const float n1_0 = __fadd_rn(__fadd_rn(__fmul_rn(ax0, ax0), __fmul_rn(ay0, ay0)),
                                 __fmul_rn(az0, az0));
    const float n1_1 = __fadd_rn(__fadd_rn(__fmul_rn(ax1, ax1), __fmul_rn(ay1, ay1)),
                                 __fmul_rn(az1, az1));

    const u64 qx0 = pk2c(ax0, ax0), qy0 = pk2c(ay0, ay0), qz0 = pk2c(az0, az0);
    const u64 qx1 = pk2c(ax1, ax1), qy1 = pk2c(ay1, ay1), qz1 = pk2c(az1, az1);
    const u64 N10 = pk2c(n1_0, n1_0), N11 = pk2c(n1_1, n1_1);
    const u64 M2  = pk2c(-2.0f, -2.0f);

    const float* s2b = S2 + (size_t)b * M * 3;
    const float INF = __int_as_float(0x7f800000);

    float cmin0[NCHUNK], cmin1[NCHUNK];
#pragma unroll
    for (int t = 0; t < NTILE; ++t) {
        for (int j = tid; j < TILE; j += THREADS) {
            const float* q = s2b + 3 * (t * TILE + j);
            float x = q[0], y = q[1], z = q[2];
            xs[j] = x; ys[j] = y; zs[j] = z;
            ws[j] = __fadd_rn(__fadd_rn(__fmul_rn(x, x), __fmul_rn(y, y)),
                              __fmul_rn(z, z));
        }
        __syncthreads();

#pragma unroll
        for (int c = 0; c < CPT; ++c) {
            const int off = g * QTR + c * CHUNK;
            float a0e = INF, a0o = INF, a1e = INF, a1o = INF;
#pragma unroll 8
            for (int k = 0; k < CHUNK; k += 4) {
                ulonglong2 X = *reinterpret_cast<const ulonglong2*>(xs + off + k);
                ulonglong2 Y = *reinterpret_cast<const ulonglong2*>(ys + off + k);
                ulonglong2 Z = *reinterpret_cast<const ulonglong2*>(zs + off + k);
                ulonglong2 W = *reinterpret_cast<const ulonglong2*>(ws + off + k);
                {
                    u64 c01 = fma2_(qz0, Z.x, fma2_(qy0, Y.x, mul2(qx0, X.x)));
                    u64 c23 = fma2_(qz0, Z.y, fma2_(qy0, Y.y, mul2(qx0, X.y)));
                    u64 d01 = add2(fma2_(c01, M2, N10), W.x);
                    u64 d23 = add2(fma2_(c23, M2, N10), W.y);
                    a0e = fminf(a0e, lo2(d01)); a0o = fminf(a0o, hi2(d01));
                    a0e = fminf(a0e, lo2(d23)); a0o = fminf(a0o, hi2(d23));
                }
                {
                    u64 c01 = fma2_(qz1, Z.x, fma2_(qy1, Y.x, mul2(qx1, X.x)));
                    u64 c23 = fma2_(qz1, Z.y, fma2_(qy1, Y.y, mul2(qx1, X.y)));
                    u64 d01 = add2(fma2_(c01, M2, N11), W.x);
                    u64 d23 = add2(fma2_(c23, M2, N11), W.y);
                    a1e = fminf(a1e, lo2(d01)); a1o = fminf(a1o, hi2(d01));
                    a1e = fminf(a1e, lo2(d23)); a1o = fminf(a1o, hi2(d23));
                }
            }
            cmin0[t * CPT + c] = fminf(a0e, a0o);
            cmin1[t * CPT + c] = fminf(a1e, a1o);
        }
        __syncthreads();
    }

    // winning chunk per query (smallest chunk id on value ties)
    float m0 = cmin0[0], m1 = cmin1[0];
#pragma unroll
    for (int c = 1; c < NCHUNK; ++c) { m0 = fminf(m0, cmin0[c]); m1 = fminf(m1, cmin1[c]); }
    int cc0 = 0, cc1 = 0;
#pragma unroll
    for (int c = NCHUNK - 1; c >= 0; --c) {
        if (cmin0[c] == m0) cc0 = c;
        if (cmin1[c] == m1) cc1 = c;
    }
    const int base0 = (cc0 / CPT) * TILE + g * QTR + (cc0 % CPT) * CHUNK;
    const int base1 = (cc1 / CPT) * TILE + g * QTR + (cc1 % CPT) * CHUNK;

    if (valid) {
        pv[g][ql0] = m0;  pb[g][ql0] = base0;
        pv[g][ql1] = m1;  pb[g][ql1] = base1;
    }
    __syncthreads();

    // merge groups: value, then smaller base on exact ties
    if (tid < qcount) {
        float bv = pv[0][tid];
        int   bb = pb[0][tid];
#pragma unroll
        for (int gg = 1; gg < G; ++gg) {
            float v  = pv[gg][tid];
            int   bs = pb[gg][tid];
            if (v < bv || (v == bv && bs < bb)) { bv = v; bb = bs; }
        }
        g_base[b * NQ + qbase + tid] = bb;
    }
}

// ---------------- Kernel 2: warp-per-query coalesced chunk rescan ----------------
#define K2_THREADS 256
#define K2_WPB     (K2_THREADS / 32)

__global__ __launch_bounds__(K2_THREADS, 1)
void SidedDistance_pass2(const float* __restrict__ S1,
                         const float* __restrict__ S2,
                         float* __restrict__ out)
{
    const int qid  = (blockIdx.x * K2_WPB) + (threadIdx.x >> 5);
    const int lane = threadIdx.x & 31;
    const int b    = qid >> 13;
    const int base = g_base[qid];

    const float* s1q = S1 + (size_t)qid * 3;
    const float ax = s1q[0], ay = s1q[1], az = s1q[2];
    const float n1 = __fadd_rn(__fadd_rn(__fmul_rn(ax, ax), __fmul_rn(ay, ay)),
                               __fmul_rn(az, az));

    const float* s2b = S2 + (size_t)b * M * 3;

    float best = __int_as_float(0x7f800000);
    int   bj   = base;
#pragma unroll
    for (int r = 0; r < CHUNK / 32; ++r) {
        const int j = base + r * 32 + lane;
        const float* q = s2b + 3 * j;
        float x = q[0], y = q[1], z = q[2];
        float n2 = __fadd_rn(__fadd_rn(__fmul_rn(x, x), __fmul_rn(y, y)),
                             __fmul_rn(z, z));
        float cr = __fmaf_rn(az, z, __fmaf_rn(ay, y, __fmul_rn(ax, x)));
        float d  = __fadd_rn(__fmaf_rn(cr, -2.0f, n1), n2);
        if (d < best) { best = d; bj = j; }
    }
#pragma unroll
    for (int m = 16; m >= 1; m >>= 1) {
        float v2 = __shfl_xor_sync(0xffffffffu, best, m);
        int   j2 = __shfl_xor_sync(0xffffffffu, bj,   m);
        if (v2 < best || (v2 == best && j2 < bj)) { best = v2; bj = j2; }
    }
    if (lane == 0) out[qid] = (float)bj;
}

extern "C" void kernel_launch(void* const* d_in, const int* in_sizes, int n_in,
                              void* d_out, int out_size)
{
    const float* S1 = (const float*)d_in[0];
    const float* S2 = (const float*)d_in[1];
    float* out = (float*)d_out;

    SidedDistance_pass1<<<NBATCH * QCHUNKS, THREADS>>>(S1, S2);
    SidedDistance_pass2<<<(NBATCH * NQ) / K2_WPB, K2_THREADS>>>(S1, S2, out);
}

// round 11
// speedup vs baseline: 1.5263x; 1.5263x over previous
#include <cuda_runtime.h>

// SidedDistance: argmin_j ||S1[b,n]-S2[b,j]||^2, B=4, N=M=8192. Output = float32 indices.
//
// Bit-exact contract (validated R5/R7/R8): reproduce reference f32 lowering exactly:
//   cross = fma(z,sz, fma(y,sy, fl(x*sx)))
//   n     = fl(fl(fl(x^2)+fl(y^2))+fl(z^2))
//   d2    = fl(fl(n1 - 2*cross) + n2)     [== fl(fma(cross,-2,n1) + n2), 2c exact]
//   argmin: first index achieving the min.
//
// R10 post-mortem: min.f32x2 not supported by ptxas -> reverted to R8's scalar FMNMX
// with mov.b64 alias unpack (proven). New this round: stage the FULL S2[b] (128 KB
// dynamic smem) once, removing the 4x per-tile staging stalls + 6 of 8 barriers
// (1 block/SM has nothing to hide cold-LDG latency behind).
//
// K1: packed f32x2 value-only min, per-chunk(256) memoized; winning chunk per query
//     (value, then smaller base) -> g_base. Broadcast LDS only.
// K2: one warp per query, coalesced rescan of winning chunk, exact arithmetic,
//     (value, then index) warp argmin-reduce.

#define NBATCH   4
#define NQ       8192
#define M        8192
#define THREADS  512
#define G        4
#define SLOTS    128
#define QB       256                  // queries per block
#define CPG      (M / G)              // 2048 candidates per group
#define CHUNK    256
#define NCHUNK   (CPG / CHUNK)        // 8
#define BLOCKS_PER_BATCH (NQ / QB)    // 32

#define DYN_SMEM_BYTES (M * 16)       // 131072: xs|ys|zs|ws, each M floats

typedef unsigned long long u64;

__device__ int g_base[NBATCH * NQ];

__device__ __forceinline__ u64 pk2(float lo, float hi) {
    u64 r; asm("mov.b64 %0, {%1, %2};" : "=l"(r) : "f"(lo), "f"(hi)); return r;
}
__device__ __forceinline__ void upk2(u64 v, float& lo, float& hi) {
    asm("mov.b64 {%0, %1}, %2;" : "=f"(lo), "=f"(hi) : "l"(v));
}
__device__ __forceinline__ u64 mul2(u64 a, u64 b) {
    u64 r; asm("mul.rn.f32x2 %0, %1, %2;" : "=l"(r) : "l"(a), "l"(b)); return r;
}
__device__ __forceinline__ u64 add2(u64 a, u64 b) {
    u64 r; asm("add.rn.f32x2 %0, %1, %2;" : "=l"(r) : "l"(a), "l"(b)); return r;
}
__device__ __forceinline__ u64 fma2_(u64 a, u64 b, u64 c) {
    u64 r; asm("fma.rn.f32x2 %0, %1, %2, %3;" : "=l"(r) : "l"(a), "l"(b), "l"(c)); return r;
}

// ---------------- Kernel 1: value-only min, chunk selection ----------------
__global__ __launch_bounds__(THREADS, 1)
void SidedDistance_pass1(const float* __restrict__ S1,
                         const float* __restrict__ S2)
{
    extern __shared__ __align__(16) float dyn[];
    float* xs = dyn;                 // [M]
    float* ys = dyn + M;             // [M]
    float* zs = dyn + 2 * M;         // [M]
    float* ws = dyn + 3 * M;         // [M]
    __shared__ float pv[G][QB];
    __shared__ int   pb[G][QB];

    const int b     = blockIdx.x >> 5;
    const int qc    = blockIdx.x & 31;
    const int qbase = qc * QB;
    const int tid   = threadIdx.x;
    const int slot  = tid & (SLOTS - 1);
    const int g     = tid >> 7;
    const int ql0   = 2 * slot;
    const int ql1   = 2 * slot + 1;

    // ---- stage ALL of S2[b] once (SoA, n2 with reference rounding) ----
    const float* s2b = S2 + (size_t)b * M * 3;
    for (int j = tid; j < M; j += THREADS) {
        const float* q = s2b + 3 * j;
        float x = q[0], y = q[1], z = q[2];
        xs[j] = x; ys[j] = y; zs[j] = z;
        ws[j] = __fadd_rn(__fadd_rn(__fmul_rn(x, x), __fmul_rn(y, y)),
                          __fmul_rn(z, z));
    }

    // queries + n1 (reference rounding)
    const float* s1b = S1 + ((size_t)b * NQ + qbase) * 3;
    const float ax0 = s1b[3 * ql0 + 0], ay0 = s1b[3 * ql0 + 1], az0 = s1b[3 * ql0 + 2];
    const float ax1 = s1b[3 * ql1 + 0], ay1 = s1b[3 * ql1 + 1], az1 = s1b[3 * ql1 + 2];
    const float n1_0 = __fadd_rn(__fadd_rn(__fmul_rn(ax0, ax0), __fmul_rn(ay0, ay0)),
                                 __fmul_rn(az0, az0));
    const float n1_1 = __fadd_rn(__fadd_rn(__fmul_rn(ax1, ax1), __fmul_rn(ay1, ay1)),
                                 __fmul_rn(az1, az1));

    const u64 qx0 = pk2(ax0, ax0), qy0 = pk2(ay0, ay0), qz0 = pk2(az0, az0);
    const u64 qx1 = pk2(ax1, ax1), qy1 = pk2(ay1, ay1), qz1 = pk2(az1, az1);
    const u64 N10 = pk2(n1_0, n1_0), N11 = pk2(n1_1, n1_1);
    const u64 M2  = pk2(-2.0f, -2.0f);

    const float INF = __int_as_float(0x7f800000);

    __syncthreads();

    // ---- pass 1: per-chunk value-only mins over this group's 2048 candidates ----
    float cmin0[NCHUNK], cmin1[NCHUNK];
#pragma unroll
    for (int c = 0; c < NCHUNK; ++c) {
        const int off = g * CPG + c * CHUNK;
        float a0e = INF, a0o = INF, a1e = INF, a1o = INF;
#pragma unroll 8
        for (int k = 0; k < CHUNK; k += 4) {
            ulonglong2 X = *reinterpret_cast<const ulonglong2*>(xs + off + k);
            ulonglong2 Y = *reinterpret_cast<const ulonglong2*>(ys + off + k);
            ulonglong2 Z = *reinterpret_cast<const ulonglong2*>(zs + off + k);
            ulonglong2 W = *reinterpret_cast<const ulonglong2*>(ws + off + k);
            float l, h;
            {
                u64 c01 = fma2_(qz0, Z.x, fma2_(qy0, Y.x, mul2(qx0, X.x)));
                u64 c23 = fma2_(qz0, Z.y, fma2_(qy0, Y.y, mul2(qx0, X.y)));
                u64 d01 = add2(fma2_(c01, M2, N10), W.x);
                u64 d23 = add2(fma2_(c23, M2, N10), W.y);
                upk2(d01, l, h); a0e = fminf(a0e, l); a0o = fminf(a0o, h);
                upk2(d23, l, h); a0e = fminf(a0e, l); a0o = fminf(a0o, h);
            }
            {
                u64 c01 = fma2_(qz1, Z.x, fma2_(qy1, Y.x, mul2(qx1, X.x)));
                u64 c23 = fma2_(qz1, Z.y, fma2_(qy1, Y.y, mul2(qx1, X.y)));
                u64 d01 = add2(fma2_(c01, M2, N11), W.x);
                u64 d23 = add2(fma2_(c23, M2, N11), W.y);
                upk2(d01, l, h); a1e = fminf(a1e, l); a1o = fminf(a1o, h);
                upk2(d23, l, h); a1e = fminf(a1e, l); a1o = fminf(a1o, h);
            }
        }
        cmin0[c] = fminf(a0e, a0o);
        cmin1[c] = fminf(a1e, a1o);
    }

    // winning chunk per query (smallest chunk id on value ties)
    float m0 = cmin0[0], m1 = cmin1[0];
#pragma unroll
    for (int c = 1; c < NCHUNK; ++c) { m0 = fminf(m0, cmin0[c]); m1 = fminf(m1, cmin1[c]); }
    int cc0 = 0, cc1 = 0;
#pragma unroll
    for (int c = NCHUNK - 1; c >= 0; --c) {
        if (cmin0[c] == m0) cc0 = c;
        if (cmin1[c] == m1) cc1 = c;
    }
    const int base0 = g * CPG + cc0 * CHUNK;
    const int base1 = g * CPG + cc1 * CHUNK;

    pv[g][ql0] = m0;  pb[g][ql0] = base0;
    pv[g][ql1] = m1;  pb[g][ql1] = base1;
    __syncthreads();

    // merge groups: value, then smaller base on exact ties
    if (tid < QB) {
        float bv = pv[0][tid];
        int   bb = pb[0][tid];
#pragma unroll
        for (int gg = 1; gg < G; ++gg) {
            float v  = pv[gg][tid];
            int   bs = pb[gg][tid];
            if (v < bv || (v == bv && bs < bb)) { bv = v; bb = bs; }
        }
        g_base[b * NQ + qbase + tid] = bb;
    }
}

// ---------------- Kernel 2: warp-per-query coalesced chunk rescan ----------------
#define K2_THREADS 256
#define K2_WPB     (K2_THREADS / 32)

__global__ __launch_bounds__(K2_THREADS, 1)
void SidedDistance_pass2(const float* __restrict__ S1,
                         const float* __restrict__ S2,
                         float* __restrict__ out)
{
    const int qid  = (blockIdx.x * K2_WPB) + (threadIdx.x >> 5);
    const int lane = threadIdx.x & 31;
    const int b    = qid >> 13;
    const int base = g_base[qid];

    const float* s1q = S1 + (size_t)qid * 3;
    const float ax = s1q[0], ay = s1q[1], az = s1q[2];
    const float n1 = __fadd_rn(__fadd_rn(__fmul_rn(ax, ax), __fmul_rn(ay, ay)),
                               __fmul_rn(az, az));

    const float* s2b = S2 + (size_t)b * M * 3;

    float best = __int_as_float(0x7f800000);
    int   bj   = base;
#pragma unroll
    for (int r = 0; r < CHUNK / 32; ++r) {
        const int j = base + r * 32 + lane;
        const float* q = s2b + 3 * j;
        float x = q[0], y = q[1], z = q[2];
        float n2 = __fadd_rn(__fadd_rn(__fmul_rn(x, x), __fmul_rn(y, y)),
                             __fmul_rn(z, z));
        float cr = __fmaf_rn(az, z, __fmaf_rn(ay, y, __fmul_rn(ax, x)));
        float d  = __fadd_rn(__fmaf_rn(cr, -2.0f, n1), n2);
        if (d < best) { best = d; bj = j; }
    }
#pragma unroll
    for (int m = 16; m >= 1; m >>= 1) {
        float v2 = __shfl_xor_sync(0xffffffffu, best, m);
        int   j2 = __shfl_xor_sync(0xffffffffu, bj,   m);
        if (v2 < best || (v2 == best && j2 < bj)) { best = v2; bj = j2; }
    }
    if (lane == 0) out[qid] = (float)bj;
}

extern "C" void kernel_launch(void* const* d_in, const int* in_sizes, int n_in,
                              void* d_out, int out_size)
{
    const float* S1 = (const float*)d_in[0];
    const float* S2 = (const float*)d_in[1];
    float* out = (float*)d_out;

    cudaFuncSetAttribute(SidedDistance_pass1,
                         cudaFuncAttributeMaxDynamicSharedMemorySize, DYN_SMEM_BYTES);

    SidedDistance_pass1<<<NBATCH * BLOCKS_PER_BATCH, THREADS, DYN_SMEM_BYTES>>>(S1, S2);
    SidedDistance_pass2<<<(NBATCH * NQ) / K2_WPB, K2_THREADS>>>(S1, S2, out);
}

// round 12
// speedup vs baseline: 1.6361x; 1.0719x over previous
#include <cuda_runtime.h>

// SidedDistance: argmin_j ||S1[b,n]-S2[b,j]||^2, B=4, N=M=8192. Output = float32 indices.
//
// Bit-exact contract (validated R5/R7/R8/R11): reproduce reference f32 lowering exactly:
//   cross = fma(z,sz, fma(y,sy, fl(x*sx)))
//   n     = fl(fl(fl(x^2)+fl(y^2))+fl(z^2))
//   d2    = fl(fl(n1 - 2*cross) + n2)     [== fl(fma(cross,-2,n1) + n2), 2c exact]
//   argmin: first index achieving the min.
//
// R11 post-mortem: pass2-as-kernel re-reads 96MB from L2 (13.4us). This round: FUSE the
// rescan — candidates are still resident in smem after pass1, so each warp rescans the
// winning 256-cand chunk for 16 queries from SoA smem (lane-stride-1, conflict-free),
// exact scalar arithmetic, (value, then index) warp argmin-reduce. One kernel total.

#define NBATCH   4
#define NQ       8192
#define M        8192
#define THREADS  512
#define G        4
#define SLOTS    128
#define QB       256                  // queries per block
#define CPG      (M / G)              // 2048 candidates per group
#define CHUNK    256
#define NCHUNK   (CPG / CHUNK)        // 8
#define BLOCKS_PER_BATCH (NQ / QB)    // 32
#define QPW      (QB / (THREADS / 32))  // 16 queries per warp in rescan

#define DYN_SMEM_BYTES (M * 16)       // 131072: xs|ys|zs|ws, each M floats

typedef unsigned long long u64;

__device__ __forceinline__ u64 pk2(float lo, float hi) {
    u64 r; asm("mov.b64 %0, {%1, %2};" : "=l"(r) : "f"(lo), "f"(hi)); return r;
}
__device__ __forceinline__ void upk2(u64 v, float& lo, float& hi) {
    asm("mov.b64 {%0, %1}, %2;" : "=f"(lo), "=f"(hi) : "l"(v));
}
__device__ __forceinline__ u64 mul2(u64 a, u64 b) {
    u64 r; asm("mul.rn.f32x2 %0, %1, %2;" : "=l"(r) : "l"(a), "l"(b)); return r;
}
__device__ __forceinline__ u64 add2(u64 a, u64 b) {
    u64 r; asm("add.rn.f32x2 %0, %1, %2;" : "=l"(r) : "l"(a), "l"(b)); return r;
}
__device__ __forceinline__ u64 fma2_(u64 a, u64 b, u64 c) {
    u64 r; asm("fma.rn.f32x2 %0, %1, %2, %3;" : "=l"(r) : "l"(a), "l"(b), "l"(c)); return r;
}

__global__ __launch_bounds__(THREADS, 1)
void SidedDistance_fused(const float* __restrict__ S1,
                         const float* __restrict__ S2,
                         float* __restrict__ out)
{
    extern __shared__ __align__(16) float dyn[];
    float* xs = dyn;                 // [M]
    float* ys = dyn + M;             // [M]
    float* zs = dyn + 2 * M;         // [M]
    float* ws = dyn + 3 * M;         // [M]
    __shared__ float pv[G][QB];
    __shared__ int   pb[G][QB];
    __shared__ int   mb[QB];         // merged winning-chunk base per query

    const int b     = blockIdx.x >> 5;
    const int qc    = blockIdx.x & 31;
    const int qbase = qc * QB;
    const int tid   = threadIdx.x;
    const int slot  = tid & (SLOTS - 1);
    const int g     = tid >> 7;
    const int ql0   = 2 * slot;
    const int ql1   = 2 * slot + 1;

    // ---- stage ALL of S2[b] once (SoA, n2 with reference rounding) ----
    const float* s2b = S2 + (size_t)b * M * 3;
    for (int j = tid; j < M; j += THREADS) {
        const float* q = s2b + 3 * j;
        float x = q[0], y = q[1], z = q[2];
        xs[j] = x; ys[j] = y; zs[j] = z;
        ws[j] = __fadd_rn(__fadd_rn(__fmul_rn(x, x), __fmul_rn(y, y)),
                          __fmul_rn(z, z));
    }

    // queries + n1 (reference rounding)
    const float* s1b = S1 + ((size_t)b * NQ + qbase) * 3;
    const float ax0 = s1b[3 * ql0 + 0], ay0 = s1b[3 * ql0 + 1], az0 = s1b[3 * ql0 + 2];
    const float ax1 = s1b[3 * ql1 + 0], ay1 = s1b[3 * ql1 + 1], az1 = s1b[3 * ql1 + 2];
    const float n1_0 = __fadd_rn(__fadd_rn(__fmul_rn(ax0, ax0), __fmul_rn(ay0, ay0)),
                                 __fmul_rn(az0, az0));
    const float n1_1 = __fadd_rn(__fadd_rn(__fmul_rn(ax1, ax1), __fmul_rn(ay1, ay1)),
                                 __fmul_rn(az1, az1));

    const u64 qx0 = pk2(ax0, ax0), qy0 = pk2(ay0, ay0), qz0 = pk2(az0, az0);
    const u64 qx1 = pk2(ax1, ax1), qy1 = pk2(ay1, ay1), qz1 = pk2(az1, az1);
    const u64 N10 = pk2(n1_0, n1_0), N11 = pk2(n1_1, n1_1);
    const u64 M2  = pk2(-2.0f, -2.0f);

    const float INF = __int_as_float(0x7f800000);

    __syncthreads();

    // ---- pass 1: per-chunk value-only mins over this group's 2048 candidates ----
    float cmin0[NCHUNK], cmin1[NCHUNK];
#pragma unroll
    for (int c = 0; c < NCHUNK; ++c) {
        const int off = g * CPG + c * CHUNK;
        float a0e = INF, a0o = INF, a1e = INF, a1o = INF;
#pragma unroll 8
        for (int k = 0; k < CHUNK; k += 4) {
            ulonglong2 X = *reinterpret_cast<const ulonglong2*>(xs + off + k);
            ulonglong2 Y = *reinterpret_cast<const ulonglong2*>(ys + off + k);
            ulonglong2 Z = *reinterpret_cast<const ulonglong2*>(zs + off + k);
            ulonglong2 W = *reinterpret_cast<const ulonglong2*>(ws + off + k);
            float l, h;
            {
                u64 c01 = fma2_(qz0, Z.x, fma2_(qy0, Y.x, mul2(qx0, X.x)));
                u64 c23 = fma2_(qz0, Z.y, fma2_(qy0, Y.y, mul2(qx0, X.y)));
                u64 d01 = add2(fma2_(c01, M2, N10), W.x);
                u64 d23 = add2(fma2_(c23, M2, N10), W.y);
                upk2(d01, l, h); a0e = fminf(a0e, l); a0o = fminf(a0o, h);
                upk2(d23, l, h); a0e = fminf(a0e, l); a0o = fminf(a0o, h);
            }
            {
                u64 c01 = fma2_(qz1, Z.x, fma2_(qy1, Y.x, mul2(qx1, X.x)));
                u64 c23 = fma2_(qz1, Z.y, fma2_(qy1, Y.y, mul2(qx1, X.y)));
                u64 d01 = add2(fma2_(c01, M2, N11), W.x);
                u64 d23 = add2(fma2_(c23, M2, N11), W.y);
                upk2(d01, l, h); a1e = fminf(a1e, l); a1o = fminf(a1o, h);
                upk2(d23, l, h); a1e = fminf(a1e, l); a1o = fminf(a1o, h);
            }
        }
        cmin0[c] = fminf(a0e, a0o);
        cmin1[c] = fminf(a1e, a1o);
    }

    // winning chunk per query (smallest chunk id on value ties)
    float m0 = cmin0[0], m1 = cmin1[0];
#pragma unroll
    for (int c = 1; c < NCHUNK; ++c) { m0 = fminf(m0, cmin0[c]); m1 = fminf(m1, cmin1[c]); }
    int cc0 = 0, cc1 = 0;
#pragma unroll
    for (int c = NCHUNK - 1; c >= 0; --c) {
        if (cmin0[c] == m0) cc0 = c;
        if (cmin1[c] == m1) cc1 = c;
    }

    pv[g][ql0] = m0;  pb[g][ql0] = g * CPG + cc0 * CHUNK;
    pv[g][ql1] = m1;  pb[g][ql1] = g * CPG + cc1 * CHUNK;
    __syncthreads();

    // merge groups: value, then smaller base on exact ties
    if (tid < QB) {
        float bv = pv[0][tid];
        int   bb = pb[0][tid];
#pragma unroll
        for (int gg = 1; gg < G; ++gg) {
            float v  = pv[gg][tid];
            int   bs = pb[gg][tid];
            if (v < bv || (v == bv && bs < bb)) { bv = v; bb = bs; }
        }
        mb[tid] = bb;
    }
    __syncthreads();

    // ---- fused rescan: each warp handles QPW queries from smem (conflict-free) ----
    const int warp = tid >> 5;
    const int lane = tid & 31;
    for (int i = 0; i < QPW; ++i) {
        const int q    = warp * QPW + i;
        const int base = mb[q];

        // query coords (broadcast, L1-warm) + n1 (reference rounding)
        const float* s1q = s1b + 3 * q;
        const float ax = s1q[0], ay = s1q[1], az = s1q[2];
        const float n1 = __fadd_rn(__fadd_rn(__fmul_rn(ax, ax), __fmul_rn(ay, ay)),
                                   __fmul_rn(az, az));

        float best = INF;
        int   bj   = base;
#pragma unroll
        for (int r = 0; r < CHUNK / 32; ++r) {
            const int j = base + r * 32 + lane;       // stride-1 across lanes
            float x = xs[j], y = ys[j], z = zs[j], w = ws[j];
            float cr = __fmaf_rn(az, z, __fmaf_rn(ay, y, __fmul_rn(ax, x)));
            float d  = __fadd_rn(__fmaf_rn(cr, -2.0f, n1), w);
            if (d < best) { best = d; bj = j; }       // ascending => first idx per lane
        }
        // warp argmin reduce: value, then smaller index on exact ties
#pragma unroll
        for (int m = 16; m >= 1; m >>= 1) {
            float v2 = __shfl_xor_sync(0xffffffffu, best, m);
            int   j2 = __shfl_xor_sync(0xffffffffu, bj,   m);
            if (v2 < best || (v2 == best && j2 < bj)) { best = v2; bj = j2; }
        }
        if (lane == 0) out[(size_t)b * NQ + qbase + q] = (float)bj;
    }
}

extern "C" void kernel_launch(void* const* d_in, const int* in_sizes, int n_in,
                              void* d_out, int out_size)
{
    const float* S1 = (const float*)d_in[0];
    const float* S2 = (const float*)d_in[1];
    float* out = (float*)d_out;

    cudaFuncSetAttribute(SidedDistance_fused,
                         cudaFuncAttributeMaxDynamicSharedMemorySize, DYN_SMEM_BYTES);

    SidedDistance_fused<<<NBATCH * BLOCKS_PER_BATCH, THREADS, DYN_SMEM_BYTES>>>(S1, S2, out);
}

// round 13
// speedup vs baseline: 1.6462x; 1.0061x over previous
#include <cuda_runtime.h>

// SidedDistance: argmin_j ||S1[b,n]-S2[b,j]||^2, B=4, N=M=8192. Output = float32 indices.
//
// Bit-exact contract (validated R5/R7/R8/R11/R12): reproduce reference f32 lowering:
//   cross = fma(z,sz, fma(y,sy, fl(x*sx)))
//   n     = fl(fl(fl(x^2)+fl(y^2))+fl(z^2))
//   d2    = fl(fl(n1 - 2*cross) + n2)     [== fl(fma(cross,-2,n1) + n2), 2c exact]
//   argmin: first index achieving the min.
//
// R12 post-mortem: issue=51%, occ=25% (4 warps/SMSP, reg-capped). This round: 1024
// threads/block (8 groups x 128 slots, CPG=1024), same 128KB full-residency S2 stage
// -> 8 warps/SMSP at half the per-warp work. __launch_bounds__(1024,1) caps regs at 64.
// Fused smem rescan preserved (full residency).

#define NBATCH   4
#define NQ       8192
#define M        8192
#define THREADS  1024
#define G        8
#define SLOTS    128
#define QB       256                  // queries per block (2 per slot)
#define CPG      (M / G)              // 1024 candidates per group
#define CHUNK    256
#define NCHUNK   (CPG / CHUNK)        // 4
#define BLOCKS_PER_BATCH (NQ / QB)    // 32
#define QPW      (QB / (THREADS / 32))  // 8 queries per warp in rescan

#define DYN_SMEM_BYTES (M * 16)       // 131072: xs|ys|zs|ws

typedef unsigned long long u64;

__device__ __forceinline__ u64 pk2(float lo, float hi) {
    u64 r; asm("mov.b64 %0, {%1, %2};" : "=l"(r) : "f"(lo), "f"(hi)); return r;
}
__device__ __forceinline__ void upk2(u64 v, float& lo, float& hi) {
    asm("mov.b64 {%0, %1}, %2;" : "=f"(lo), "=f"(hi) : "l"(v));
}
__device__ __forceinline__ u64 mul2(u64 a, u64 b) {
    u64 r; asm("mul.rn.f32x2 %0, %1, %2;" : "=l"(r) : "l"(a), "l"(b)); return r;
}
__device__ __forceinline__ u64 add2(u64 a, u64 b) {
    u64 r; asm("add.rn.f32x2 %0, %1, %2;" : "=l"(r) : "l"(a), "l"(b)); return r;
}
__device__ __forceinline__ u64 fma2_(u64 a, u64 b, u64 c) {
    u64 r; asm("fma.rn.f32x2 %0, %1, %2, %3;" : "=l"(r) : "l"(a), "l"(b), "l"(c)); return r;
}

__global__ __launch_bounds__(THREADS, 1)
void SidedDistance_fused(const float* __restrict__ S1,
                         const float* __restrict__ S2,
                         float* __restrict__ out)
{
    extern __shared__ __align__(16) float dyn[];
    float* xs = dyn;                 // [M]
    float* ys = dyn + M;             // [M]
    float* zs = dyn + 2 * M;         // [M]
    float* ws = dyn + 3 * M;         // [M]
    __shared__ float pv[G][QB];      // 8 KB
    __shared__ int   pb[G][QB];      // 8 KB
    __shared__ int   mb[QB];         // 1 KB

    const int b     = blockIdx.x >> 5;
    const int qc    = blockIdx.x & 31;
    const int qbase = qc * QB;
    const int tid   = threadIdx.x;
    const int slot  = tid & (SLOTS - 1);
    const int g     = tid >> 7;               // 0..7
    const int ql0   = 2 * slot;
    const int ql1   = 2 * slot + 1;

    // ---- stage ALL of S2[b] once (SoA, n2 with reference rounding) ----
    const float* s2b = S2 + (size_t)b * M * 3;
    for (int j = tid; j < M; j += THREADS) {
        const float* q = s2b + 3 * j;
        float x = q[0], y = q[1], z = q[2];
        xs[j] = x; ys[j] = y; zs[j] = z;
        ws[j] = __fadd_rn(__fadd_rn(__fmul_rn(x, x), __fmul_rn(y, y)),
                          __fmul_rn(z, z));
    }

    // queries + n1 (reference rounding)
    const float* s1b = S1 + ((size_t)b * NQ + qbase) * 3;
    const float ax0 = s1b[3 * ql0 + 0], ay0 = s1b[3 * ql0 + 1], az0 = s1b[3 * ql0 + 2];
    const float ax1 = s1b[3 * ql1 + 0], ay1 = s1b[3 * ql1 + 1], az1 = s1b[3 * ql1 + 2];
    const float n1_0 = __fadd_rn(__fadd_rn(__fmul_rn(ax0, ax0), __fmul_rn(ay0, ay0)),
                                 __fmul_rn(az0, az0));
    const float n1_1 = __fadd_rn(__fadd_rn(__fmul_rn(ax1, ax1), __fmul_rn(ay1, ay1)),
                                 __fmul_rn(az1, az1));

    const u64 qx0 = pk2(ax0, ax0), qy0 = pk2(ay0, ay0), qz0 = pk2(az0, az0);
    const u64 qx1 = pk2(ax1, ax1), qy1 = pk2(ay1, ay1), qz1 = pk2(az1, az1);
    const u64 N10 = pk2(n1_0, n1_0), N11 = pk2(n1_1, n1_1);
    const u64 M2  = pk2(-2.0f, -2.0f);

    const float INF = __int_as_float(0x7f800000);

    __syncthreads();

    // ---- pass 1: per-chunk value-only mins over this group's 1024 candidates ----
    float cmin0[NCHUNK], cmin1[NCHUNK];
#pragma unroll
    for (int c = 0; c < NCHUNK; ++c) {
        const int off = g * CPG + c * CHUNK;
        float a0e = INF, a0o = INF, a1e = INF, a1o = INF;
#pragma unroll 8
        for (int k = 0; k < CHUNK; k += 4) {
            ulonglong2 X = *reinterpret_cast<const ulonglong2*>(xs + off + k);
            ulonglong2 Y = *reinterpret_cast<const ulonglong2*>(ys + off + k);
            ulonglong2 Z = *reinterpret_cast<const ulonglong2*>(zs + off + k);
            ulonglong2 W = *reinterpret_cast<const ulonglong2*>(ws + off + k);
            float l, h;
            {
                u64 c01 = fma2_(qz0, Z.x, fma2_(qy0, Y.x, mul2(qx0, X.x)));
                u64 c23 = fma2_(qz0, Z.y, fma2_(qy0, Y.y, mul2(qx0, X.y)));
                u64 d01 = add2(fma2_(c01, M2, N10), W.x);
                u64 d23 = add2(fma2_(c23, M2, N10), W.y);
                upk2(d01, l, h); a0e = fminf(a0e, l); a0o = fminf(a0o, h);
                upk2(d23, l, h); a0e = fminf(a0e, l); a0o = fminf(a0o, h);
            }
            {
                u64 c01 = fma2_(qz1, Z.x, fma2_(qy1, Y.x, mul2(qx1, X.x)));
                u64 c23 = fma2_(qz1, Z.y, fma2_(qy1, Y.y, mul2(qx1, X.y)));
                u64 d01 = add2(fma2_(c01, M2, N11), W.x);
                u64 d23 = add2(fma2_(c23, M2, N11), W.y);
                upk2(d01, l, h); a1e = fminf(a1e, l); a1o = fminf(a1o, h);
                upk2(d23, l, h); a1e = fminf(a1e, l); a1o = fminf(a1o, h);
            }
        }
        cmin0[c] = fminf(a0e, a0o);
        cmin1[c] = fminf(a1e, a1o);
    }

    // winning chunk per query (smallest chunk id on value ties)
    float m0 = cmin0[0], m1 = cmin1[0];
#pragma unroll
    for (int c = 1; c < NCHUNK; ++c) { m0 = fminf(m0, cmin0[c]); m1 = fminf(m1, cmin1[c]); }
    int cc0 = 0, cc1 = 0;
#pragma unroll
    for (int c = NCHUNK - 1; c >= 0; --c) {
        if (cmin0[c] == m0) cc0 = c;
        if (cmin1[c] == m1) cc1 = c;
    }

    pv[g][ql0] = m0;  pb[g][ql0] = g * CPG + cc0 * CHUNK;
    pv[g][ql1] = m1;  pb[g][ql1] = g * CPG + cc1 * CHUNK;
    __syncthreads();

    // merge groups: value, then smaller base on exact ties
    if (tid < QB) {
        float bv = pv[0][tid];
        int   bb = pb[0][tid];
#pragma unroll
        for (int gg = 1; gg < G; ++gg) {
            float v  = pv[gg][tid];
            int   bs = pb[gg][tid];
            if (v < bv || (v == bv && bs < bb)) { bv = v; bb = bs; }
        }
        mb[tid] = bb;
    }
    __syncthreads();

    // ---- fused rescan: each warp handles QPW queries from smem (conflict-free) ----
    const int warp = tid >> 5;
    const int lane = tid & 31;
    for (int i = 0; i < QPW; ++i) {
        const int q    = warp * QPW + i;
        const int base = mb[q];

        const float* s1q = s1b + 3 * q;
        const float ax = s1q[0], ay = s1q[1], az = s1q[2];
        const float n1 = __fadd_rn(__fadd_rn(__fmul_rn(ax, ax), __fmul_rn(ay, ay)),
                                   __fmul_rn(az, az));

        float best = INF;
        int   bj   = base;
#pragma unroll
        for (int r = 0; r < CHUNK / 32; ++r) {
            const int j = base + r * 32 + lane;       // stride-1 across lanes
            float x = xs[j], y = ys[j], z = zs[j], w = ws[j];
            float cr = __fmaf_rn(az, z, __fmaf_rn(ay, y, __fmul_rn(ax, x)));
            float d  = __fadd_rn(__fmaf_rn(cr, -2.0f, n1), w);
            if (d < best) { best = d; bj = j; }       // ascending => first idx per lane
        }
#pragma unroll
        for (int m = 16; m >= 1; m >>= 1) {
            float v2 = __shfl_xor_sync(0xffffffffu, best, m);
            int   j2 = __shfl_xor_sync(0xffffffffu, bj,   m);
            if (v2 < best || (v2 == best && j2 < bj)) { best = v2; bj = j2; }
        }
        if (lane == 0) out[(size_t)b * NQ + qbase + q] = (float)bj;
    }
}

extern "C" void kernel_launch(void* const* d_in, const int* in_sizes, int n_in,
                              void* d_out, int out_size)
{
    const float* S1 = (const float*)d_in[0];
    const float* S2 = (const float*)d_in[1];
    float* out = (float*)d_out;

    cudaFuncSetAttribute(SidedDistance_fused,
                         cudaFuncAttributeMaxDynamicSharedMemorySize, DYN_SMEM_BYTES);

    SidedDistance_fused<<<NBATCH * BLOCKS_PER_BATCH, THREADS, DYN_SMEM_BYTES>>>(S1, S2, out);
}